// round 13
// baseline (speedup 1.0000x reference)
#include <cuda_runtime.h>
#include <cuda_bf16.h>
#include <cuda_fp16.h>
#include <cstdint>
#include <math.h>

// Problem constants
constexpr int NN   = 20000;
constexpr int EE   = 320000;
constexpr int FF   = 256;
constexpr int HH   = 8;
constexpr int DD   = 64;
constexpr int HD   = 512;
constexpr int MM   = 2;
constexpr int CC   = 5;
constexpr int HIDN = 128;
constexpr int NB   = 80;
constexpr int NPAD = 20096;   // 157 * 128

// ---------------- device scratch ----------------
__device__ __half g_feat_h[MM][NN][HD];
__device__ __half g_z_h[MM][NN][HD];
__device__ float g_el[MM][NN][HH];
__device__ float g_er[MM][NN][HH];
__device__ int   g_deg[MM][NN];
__device__ int   g_rowptr[MM][NN + 1];
__device__ int   g_cur[MM][NN];
__device__ int   g_csr_src[MM][EE];
__device__ float g_w[MM * NN];
__device__ float g_wsum[MM];
__device__ float g_beta[MM];
__device__ int   g_psum[MM][NB];
__device__ int   g_boff[MM][NB];
__device__ __half g_h_hi[NPAD][FF];          // h split: fp16 hi + fp16 residual
__device__ __half g_h_lo[NPAD][FF];
__device__ __half g_Wt_h[MM][HD][FF];        // W transposed [n][k], fp16
__device__ __nv_bfloat16 g_W1t_hi[HIDN][HD];

// ---------------- helpers ----------------
__device__ __forceinline__ uint32_t pack_bf2(float x, float y) {
    __nv_bfloat162 p = __floats2bfloat162_rn(x, y);
    return *(uint32_t*)&p;
}
__device__ __forceinline__ float fast_tanh(float x) {
    float e2 = __expf(2.f * x);
    return __fdividef(e2 - 1.f, e2 + 1.f);
}
#define MMA_F16(d, a, b) \
    asm volatile( \
        "mma.sync.aligned.m16n8k16.row.col.f32.f16.f16.f32 " \
        "{%0,%1,%2,%3}, {%4,%5,%6,%7}, {%8,%9}, {%0,%1,%2,%3};" \
        : "+f"((d)[0]), "+f"((d)[1]), "+f"((d)[2]), "+f"((d)[3]) \
        : "r"((a)[0]), "r"((a)[1]), "r"((a)[2]), "r"((a)[3]), \
          "r"((b)[0]), "r"((b)[1]))
#define MMA_BF16(d, a, b) \
    asm volatile( \
        "mma.sync.aligned.m16n8k16.row.col.f32.bf16.bf16.f32 " \
        "{%0,%1,%2,%3}, {%4,%5,%6,%7}, {%8,%9}, {%0,%1,%2,%3};" \
        : "+f"((d)[0]), "+f"((d)[1]), "+f"((d)[2]), "+f"((d)[3]) \
        : "r"((a)[0]), "r"((a)[1]), "r"((a)[2]), "r"((a)[3]), \
          "r"((b)[0]), "r"((b)[1]))
#define LDSM_X4(r, addr) \
    asm volatile("ldmatrix.sync.aligned.m8n8.x4.shared.b16 {%0,%1,%2,%3}, [%4];" \
        : "=r"((r)[0]), "=r"((r)[1]), "=r"((r)[2]), "=r"((r)[3]) : "r"(addr))
#define CP_ASYNC16(smem_u32, gptr) \
    asm volatile("cp.async.cg.shared.global [%0], [%1], 16;" \
        :: "r"(smem_u32), "l"(gptr) : "memory")
#define CP_COMMIT() asm volatile("cp.async.commit_group;" ::: "memory")
#define CP_WAIT(n)  asm volatile("cp.async.wait_group %0;" :: "n"(n) : "memory")

// ---------------- conversion kernels ----------------
__global__ void conv_h_kernel(const float* __restrict__ h) {
    int idx = blockIdx.x * blockDim.x + threadIdx.x;   // one per 8 elements
    if (idx >= NPAD * FF / 8) return;
    int row = idx >> 5;
    int kk  = (idx & 31) * 8;
    uint4 hi = make_uint4(0, 0, 0, 0), lo = hi;
    if (row < NN) {
        const float* hp = &h[row * FF + kk];
        float4 a = *(const float4*)hp;
        float4 b = *(const float4*)(hp + 4);
        float v[8] = {a.x, a.y, a.z, a.w, b.x, b.y, b.z, b.w};
        __half vh[8], vl[8];
#pragma unroll
        for (int i = 0; i < 8; i++) {
            vh[i] = __float2half_rn(v[i]);
            vl[i] = __float2half_rn(v[i] - __half2float(vh[i]));
        }
        hi.x = *(uint32_t*)&vh[0]; hi.y = *(uint32_t*)&vh[2];
        hi.z = *(uint32_t*)&vh[4]; hi.w = *(uint32_t*)&vh[6];
        lo.x = *(uint32_t*)&vl[0]; lo.y = *(uint32_t*)&vl[2];
        lo.z = *(uint32_t*)&vl[4]; lo.w = *(uint32_t*)&vl[6];
    }
    *(uint4*)&g_h_hi[row][kk] = hi;
    *(uint4*)&g_h_lo[row][kk] = lo;
}

__global__ void conv_w_kernel(const float* __restrict__ W) {
    __shared__ float tile[32][33];
    int mp = blockIdx.z;
    int n0 = blockIdx.x * 32, k0 = blockIdx.y * 32;
    int tx = threadIdx.x, ty = threadIdx.y;  // 32 x 8
#pragma unroll
    for (int j = 0; j < 4; j++)
        tile[ty + j * 8][tx] = W[mp * FF * HD + (k0 + ty + j * 8) * HD + n0 + tx];
    __syncthreads();
#pragma unroll
    for (int j = 0; j < 4; j++) {
        int n = n0 + ty + j * 8, k = k0 + tx;
        g_Wt_h[mp][n][k] = __float2half_rn(tile[tx][ty + j * 8]);
    }
}

__global__ void conv_w1t_kernel(const float* __restrict__ W1) {
    __shared__ float tile[32][33];
    int n0 = blockIdx.x * 32, k0 = blockIdx.y * 32;
    int tx = threadIdx.x, ty = threadIdx.y;
#pragma unroll
    for (int j = 0; j < 4; j++)
        tile[ty + j * 8][tx] = W1[(k0 + ty + j * 8) * HIDN + n0 + tx];
    __syncthreads();
#pragma unroll
    for (int j = 0; j < 4; j++) {
        int n = n0 + ty + j * 8, k = k0 + tx;
        g_W1t_hi[n][k] = __float2bfloat16(tile[tx][ty + j * 8]);
    }
}

// ---------------- feat GEMM: 128x128 block, fp16 2-product, 2 stages --------
// Stage layout (80 B/row): A_hi 0, A_lo 10240, B_hi 20480. Stage = 30720.
constexpr int STAGE_STRIDE = 30720;
constexpr int FEAT_SMEM_BYTES = 2 * STAGE_STRIDE + 1024;

__global__ void __launch_bounds__(256, 2)
feat_mma_kernel(const float* __restrict__ al, const float* __restrict__ ar) {
    extern __shared__ char smem[];
    float* s_al = (float*)(smem + 2 * STAGE_STRIDE);
    float* s_ar = s_al + 128;
    uint32_t smem_u32;
    asm("{ .reg .u64 t; cvta.to.shared.u64 t, %1; cvt.u32.u64 %0, t; }"
        : "=r"(smem_u32) : "l"(smem));

    const int t = threadIdx.x, lane = t & 31, wid = t >> 5;
    const int wm = wid & 3, wn = wid >> 2;        // 4(m) x 2(n)
    const int rowBase = blockIdx.x * 128;
    const int colBase = blockIdx.y * 128;          // 2 heads
    const int mp      = blockIdx.z;

    if (t < 128) {
        s_al[t] = al[mp * HD + colBase + t];
        s_ar[t] = ar[mp * HD + colBase + t];
    }

    const int l_in  = lane & 7;
    const int l_t01 = (lane >> 3) & 1;
    const int l_t23 = lane >> 4;
    const uint32_t a_off0 = (uint32_t)(wm * 32 + l_in + l_t01 * 8) * 80 + l_t23 * 16;
    const uint32_t b_off0 = (uint32_t)(wn * 64 + l_in + (lane >> 4) * 8) * 80
                          + ((lane >> 3) & 1) * 16;

    const int st_row = t >> 1;            // 0..127
    const int st_q0  = (t & 1) * 2;       // 0 or 2

    auto cp_stage = [&](int kc, int buf) {
        uint32_t base = smem_u32 + buf * STAGE_STRIDE;
        const int karow = rowBase + st_row;
        const int kbrow = colBase + st_row;
#pragma unroll
        for (int q = 0; q < 2; q++) {
            uint32_t so = (uint32_t)st_row * 80 + (st_q0 + q) * 16;
            int gk = kc * 32 + (st_q0 + q) * 8;
            CP_ASYNC16(base + so,         &g_h_hi[karow][gk]);
            CP_ASYNC16(base + 10240 + so, &g_h_lo[karow][gk]);
            CP_ASYNC16(base + 20480 + so, &g_Wt_h[mp][kbrow][gk]);
        }
    };

    float d[2][8][4] = {};

    cp_stage(0, 0);
    CP_COMMIT();

    for (int kc = 0; kc < 8; kc++) {
        const int cur = kc & 1;
        if (kc < 7) {
            cp_stage(kc + 1, cur ^ 1);
            CP_COMMIT();
            CP_WAIT(1);
        } else {
            CP_WAIT(0);
        }
        __syncthreads();

        const uint32_t bufb = smem_u32 + cur * STAGE_STRIDE;

#pragma unroll
        for (int ks = 0; ks < 2; ks++) {
            const uint32_t kb = (uint32_t)ks * 32;
            uint32_t ah[2][4], alo[2][4], bh_r[4][4];
#pragma unroll
            for (int mi = 0; mi < 2; mi++) {
                uint32_t ao = bufb + a_off0 + (uint32_t)(mi * 16) * 80 + kb;
                LDSM_X4(ah[mi], ao);
                LDSM_X4(alo[mi], ao + 10240);
            }
#pragma unroll
            for (int p = 0; p < 4; p++) {
                uint32_t bo = bufb + 20480 + b_off0 + (uint32_t)(p * 16) * 80 + kb;
                LDSM_X4(bh_r[p], bo);
            }
#pragma unroll
            for (int mi = 0; mi < 2; mi++)
#pragma unroll
                for (int p = 0; p < 4; p++) {
#pragma unroll
                    for (int q = 0; q < 2; q++) {
                        int ni = p * 2 + q;
                        uint32_t bhq[2] = { bh_r[p][q * 2], bh_r[p][q * 2 + 1] };
                        MMA_F16(d[mi][ni], ah[mi], bhq);
                        MMA_F16(d[mi][ni], alo[mi], bhq);
                    }
                }
        }
        __syncthreads();
    }

    // ---- epilogue ----
    const int head = colBase / DD + wn;
#pragma unroll
    for (int mi = 0; mi < 2; mi++) {
#pragma unroll
        for (int half = 0; half < 2; half++) {
            int r = wm * 32 + mi * 16 + half * 8 + (lane >> 2);
            int grow = rowBase + r;
            float el = 0.f, er = 0.f;
#pragma unroll
            for (int ni = 0; ni < 8; ni++) {
                float v0 = d[mi][ni][half * 2 + 0];
                float v1 = d[mi][ni][half * 2 + 1];
                int c = wn * 64 + ni * 8 + (lane & 3) * 2;
                el += v0 * s_al[c] + v1 * s_al[c + 1];
                er += v0 * s_ar[c] + v1 * s_ar[c + 1];
                if (grow < NN) {
                    __half2 hv = __floats2half2_rn(v0, v1);
                    *(__half2*)&g_feat_h[mp][grow][colBase + c] = hv;
                }
            }
            el += __shfl_xor_sync(0xffffffffu, el, 1);
            el += __shfl_xor_sync(0xffffffffu, el, 2);
            er += __shfl_xor_sync(0xffffffffu, er, 1);
            er += __shfl_xor_sync(0xffffffffu, er, 2);
            if ((lane & 3) == 0 && grow < NN) {
                g_el[mp][grow][head] = el;
                g_er[mp][grow][head] = er;
            }
        }
    }
}

// ---------------- CSR build ----------------
__global__ void count_kernel(const int* __restrict__ dst) {
    int mp = blockIdx.y;
    int e = blockIdx.x * blockDim.x + threadIdx.x;
    if (e < EE) atomicAdd(&g_deg[mp][dst[mp * EE + e]], 1);
}

__global__ void scan_partial() {
    int mp = blockIdx.y;
    int i = blockIdx.x * 256 + threadIdx.x;
    int v = (i < NN) ? g_deg[mp][i] : 0;
#pragma unroll
    for (int off = 16; off; off >>= 1) v += __shfl_xor_sync(0xffffffffu, v, off);
    __shared__ int ws[8];
    if ((threadIdx.x & 31) == 0) ws[threadIdx.x >> 5] = v;
    __syncthreads();
    if (threadIdx.x == 0) {
        int s = 0;
#pragma unroll
        for (int w = 0; w < 8; w++) s += ws[w];
        g_psum[mp][blockIdx.x] = s;
    }
}

__global__ void scan_mid() {
    int mp = blockIdx.x;
    int t = threadIdx.x, lane = t & 31, wid = t >> 5;
    int v = (t < NB) ? g_psum[mp][t] : 0;
    int x = v;
#pragma unroll
    for (int off = 1; off < 32; off <<= 1) {
        int y = __shfl_up_sync(0xffffffffu, x, off);
        if (lane >= off) x += y;
    }
    __shared__ int ws[4];
    if (lane == 31) ws[wid] = x;
    __syncthreads();
    int woff = 0;
    for (int w = 0; w < wid; w++) woff += ws[w];
    if (t < NB) g_boff[mp][t] = woff + x - v;
}

__global__ void scan_final() {
    int mp = blockIdx.y;
    int t = threadIdx.x, lane = t & 31, wid = t >> 5;
    int i = blockIdx.x * 256 + t;
    int v = (i < NN) ? g_deg[mp][i] : 0;
    int x = v;
#pragma unroll
    for (int off = 1; off < 32; off <<= 1) {
        int y = __shfl_up_sync(0xffffffffu, x, off);
        if (lane >= off) x += y;
    }
    __shared__ int ws[8];
    if (lane == 31) ws[wid] = x;
    __syncthreads();
    int woff = 0;
    for (int w = 0; w < wid; w++) woff += ws[w];
    int excl = g_boff[mp][blockIdx.x] + woff + x - v;
    if (i < NN) {
        g_rowptr[mp][i] = excl;
        g_cur[mp][i]    = excl;
        if (i == NN - 1) g_rowptr[mp][NN] = excl + v;
    }
}

__global__ void scatter_kernel(const int* __restrict__ src,
                               const int* __restrict__ dst) {
    int mp = blockIdx.y;
    int e = blockIdx.x * blockDim.x + threadIdx.x;
    if (e < EE) {
        int d = dst[mp * EE + e];
        int pos = atomicAdd(&g_cur[mp][d], 1);
        g_csr_src[mp][pos] = src[mp * EE + e];
    }
}

// ---------------- edge softmax + aggregation: warp per node -----------------
// Lane l owns dims [16l, 16l+16), all inside head l/4. No smem, no barriers.
#define ACC8(r, off) { \
    float2 f0 = __half22float2(*(__half2*)&(r).x); \
    float2 f1 = __half22float2(*(__half2*)&(r).y); \
    float2 f2 = __half22float2(*(__half2*)&(r).z); \
    float2 f3 = __half22float2(*(__half2*)&(r).w); \
    acc[(off)+0] += w * f0.x; acc[(off)+1] += w * f0.y; \
    acc[(off)+2] += w * f1.x; acc[(off)+3] += w * f1.y; \
    acc[(off)+4] += w * f2.x; acc[(off)+5] += w * f2.y; \
    acc[(off)+6] += w * f3.x; acc[(off)+7] += w * f3.y; }

__global__ void __launch_bounds__(128)
agg_kernel(const float* __restrict__ bias) {
    const int lane = threadIdx.x & 31;
    const int v = blockIdx.x * 4 + (threadIdx.x >> 5);
    const int mp = blockIdx.y;
    if (v >= NN) return;

    const int start = g_rowptr[mp][v];
    const int deg   = g_rowptr[mp][v + 1] - start;
    const int myh = lane >> 2;        // head of this lane's dims
    const int d0  = lane * 16;

    const float er = g_er[mp][v][myh];
    float acc[16];
#pragma unroll
    for (int i = 0; i < 16; i++) acc[i] = 0.f;
    float den = 0.f;

    const int* csr = &g_csr_src[mp][start];
    for (int base = 0; base < deg; base += 32) {
        const int cn = min(32, deg - base);
        int s_l = (base + lane < deg) ? csr[base + lane] : 0;
#pragma unroll 4
        for (int j = 0; j < cn; j++) {
            int s = __shfl_sync(0xffffffffu, s_l, j);
            float e = g_el[mp][s][myh] + er;
            e = (e > 0.f) ? e : 0.2f * e;
            float w = __expf(e);
            den += w;
            const uint4* fp = (const uint4*)&g_feat_h[mp][s][d0];
            uint4 r0 = fp[0];
            uint4 r1 = fp[1];
            ACC8(r0, 0);
            ACC8(r1, 8);
        }
    }

    float inv = __fdividef(1.f, fmaxf(den, 1e-9f));
    const float* b = bias + mp * HD + d0;
    __half2 hv[8];
#pragma unroll
    for (int i = 0; i < 16; i += 2) {
        float o0 = acc[i] * inv + b[i];
        float o1 = acc[i + 1] * inv + b[i + 1];
        o0 = (o0 > 0.f) ? o0 : (__expf(o0) - 1.f);
        o1 = (o1 > 0.f) ? o1 : (__expf(o1) - 1.f);
        hv[i / 2] = __floats2half2_rn(o0, o1);
    }
    uint4* zo = (uint4*)&g_z_h[mp][v][d0];
    zo[0] = *(uint4*)&hv[0];
    zo[1] = *(uint4*)&hv[4];
}

// ---------------- semantic attention: single-product bf16 MMA ---------------
constexpr int SEM_SMEM_BYTES = 9216 + 18432 + 1280;

__global__ void __launch_bounds__(256)
sem_mma_kernel(const float* __restrict__ b1, const float* __restrict__ W2) {
    extern __shared__ char smem[];
    __nv_bfloat16 (*Ah)[72] = (__nv_bfloat16(*)[72])(smem);
    __nv_bfloat16 (*Bh)[72] = (__nv_bfloat16(*)[72])(smem + 9216);
    float* s_b1 = (float*)(smem + 27648);
    float* s_w2 = s_b1 + 128;
    float* s_wr = s_w2 + 128;

    const int t = threadIdx.x, lane = t & 31, wid = t >> 5;
    const int wm = wid & 1, wn = wid >> 1;
    const int rowBase = blockIdx.x * 64;
    const __half* Zh = &g_z_h[0][0][0];

    if (t < 128) { s_b1[t] = b1[t]; s_w2[t] = W2[t]; }
    if (t < 64) s_wr[t] = 0.f;

    float d[2][4][4] = {};

    for (int kc = 0; kc < 8; kc++) {
#pragma unroll
        for (int j = 0; j < 2; j++) {
            int idx = t + j * 256;
            int row = idx >> 3, kq = (idx & 7) * 8;
            uint4 raw = *(const uint4*)&Zh[(rowBase + row) * HD + kc * 64 + kq];
            float2 f0 = __half22float2(*(__half2*)&raw.x);
            float2 f1 = __half22float2(*(__half2*)&raw.y);
            float2 f2 = __half22float2(*(__half2*)&raw.z);
            float2 f3 = __half22float2(*(__half2*)&raw.w);
            uint4 hi;
            hi.x = pack_bf2(f0.x, f0.y); hi.y = pack_bf2(f1.x, f1.y);
            hi.z = pack_bf2(f2.x, f2.y); hi.w = pack_bf2(f3.x, f3.y);
            *(uint4*)&Ah[row][kq] = hi;
        }
#pragma unroll
        for (int j = 0; j < 4; j++) {
            int idx = t + j * 256;
            int row = idx >> 3, kq = (idx & 7) * 8;
            *(uint4*)&Bh[row][kq] = *(const uint4*)&g_W1t_hi[row][kc * 64 + kq];
        }
        __syncthreads();

#pragma unroll
        for (int ks = 0; ks < 4; ks++) {
            const int kk = ks * 16 + (lane & 3) * 2;
            uint32_t ah[2][4], bh[4][2];
#pragma unroll
            for (int mi = 0; mi < 2; mi++) {
                int r = wm * 32 + mi * 16 + (lane >> 2);
                ah[mi][0] = *(const uint32_t*)&Ah[r][kk];
                ah[mi][1] = *(const uint32_t*)&Ah[r + 8][kk];
                ah[mi][2] = *(const uint32_t*)&Ah[r][kk + 8];
                ah[mi][3] = *(const uint32_t*)&Ah[r + 8][kk + 8];
            }
#pragma unroll
            for (int ni = 0; ni < 4; ni++) {
                int n = wn * 32 + ni * 8 + (lane >> 2);
                bh[ni][0] = *(const uint32_t*)&Bh[n][kk];
                bh[ni][1] = *(const uint32_t*)&Bh[n][kk + 8];
            }
#pragma unroll
            for (int mi = 0; mi < 2; mi++)
#pragma unroll
                for (int ni = 0; ni < 4; ni++)
                    MMA_BF16(d[mi][ni], ah[mi], bh[ni]);
        }
        __syncthreads();
    }

#pragma unroll
    for (int mi = 0; mi < 2; mi++) {
#pragma unroll
        for (int half = 0; half < 2; half++) {
            float p = 0.f;
#pragma unroll
            for (int ni = 0; ni < 4; ni++) {
                int c = wn * 32 + ni * 8 + (lane & 3) * 2;
                p += fast_tanh(d[mi][ni][half * 2 + 0] + s_b1[c]) * s_w2[c];
                p += fast_tanh(d[mi][ni][half * 2 + 1] + s_b1[c + 1]) * s_w2[c + 1];
            }
            p += __shfl_xor_sync(0xffffffffu, p, 1);
            p += __shfl_xor_sync(0xffffffffu, p, 2);
            if ((lane & 3) == 0)
                atomicAdd(&s_wr[wm * 32 + mi * 16 + half * 8 + (lane >> 2)], p);
        }
    }
    __syncthreads();
    if (t < 64) g_w[rowBase + t] = s_wr[t];
}

__global__ void wsum_kernel() {
    __shared__ float sp[MM];
    if (threadIdx.x < MM) sp[threadIdx.x] = 0.f;
    __syncthreads();
    int i = blockIdx.x * blockDim.x + threadIdx.x;
    if (i < MM * NN) atomicAdd(&sp[i / NN], g_w[i]);
    __syncthreads();
    if (threadIdx.x < MM) atomicAdd(&g_wsum[threadIdx.x], sp[threadIdx.x]);
}

__global__ void beta_kernel() {
    float a = g_wsum[0] / (float)NN;
    float b = g_wsum[1] / (float)NN;
    float m = fmaxf(a, b);
    float ea = __expf(a - m), eb = __expf(b - m);
    float s = ea + eb;
    g_beta[0] = ea / s;
    g_beta[1] = eb / s;
}

__global__ void pred_kernel(const float* __restrict__ pw,
                            const float* __restrict__ pb,
                            float* __restrict__ out) {
    int gwarp = (blockIdx.x * blockDim.x + threadIdx.x) >> 5;
    int lane  = threadIdx.x & 31;
    if (gwarp >= NN) return;
    float b0 = g_beta[0], b1 = g_beta[1];
    float acc[CC];
#pragma unroll
    for (int c = 0; c < CC; c++) acc[c] = 0.f;
    const __half2* z0 = (const __half2*)g_z_h[0][gwarp];
    const __half2* z1 = (const __half2*)g_z_h[1][gwarp];
#pragma unroll
    for (int i = 0; i < HD / 64; i++) {
        int d2 = lane + i * 32;
        float2 f0 = __half22float2(z0[d2]);
        float2 f1 = __half22float2(z1[d2]);
        float hv0 = b0 * f0.x + b1 * f1.x;
        float hv1 = b0 * f0.y + b1 * f1.y;
        int dd = d2 * 2;
#pragma unroll
        for (int c = 0; c < CC; c++)
            acc[c] += hv0 * __ldg(&pw[dd * CC + c]) + hv1 * __ldg(&pw[(dd + 1) * CC + c]);
    }
#pragma unroll
    for (int off = 16; off; off >>= 1)
#pragma unroll
        for (int c = 0; c < CC; c++)
            acc[c] += __shfl_xor_sync(0xffffffffu, acc[c], off);
    if (lane == 0) {
#pragma unroll
        for (int c = 0; c < CC; c++) out[gwarp * CC + c] = acc[c] + pb[c];
    }
}

// ---------------- launch ----------------
extern "C" void kernel_launch(void* const* d_in, const int* in_sizes, int n_in,
                              void* d_out, int out_size) {
    const float* h      = (const float*)d_in[0];
    const int*   src    = (const int*)d_in[1];
    const int*   dst    = (const int*)d_in[2];
    const float* W      = (const float*)d_in[3];
    const float* attn_l = (const float*)d_in[4];
    const float* attn_r = (const float*)d_in[5];
    const float* bias_g = (const float*)d_in[6];
    const float* sem_W1 = (const float*)d_in[7];
    const float* sem_b1 = (const float*)d_in[8];
    const float* sem_W2 = (const float*)d_in[9];
    const float* pred_W = (const float*)d_in[10];
    const float* pred_b = (const float*)d_in[11];
    float* out = (float*)d_out;

    static cudaStream_t s2 = nullptr;
    static cudaEvent_t ev_fork = nullptr, ev_join = nullptr;
    if (s2 == nullptr) {
        cudaStreamCreateWithFlags(&s2, cudaStreamNonBlocking);
        cudaEventCreateWithFlags(&ev_fork, cudaEventDisableTiming);
        cudaEventCreateWithFlags(&ev_join, cudaEventDisableTiming);
    }

    cudaFuncSetAttribute(feat_mma_kernel,
                         cudaFuncAttributeMaxDynamicSharedMemorySize, FEAT_SMEM_BYTES);
    cudaFuncSetAttribute(sem_mma_kernel,
                         cudaFuncAttributeMaxDynamicSharedMemorySize, SEM_SMEM_BYTES);

    void* p_deg = nullptr;
    void* p_ws  = nullptr;
    cudaGetSymbolAddress(&p_deg, g_deg);
    cudaGetSymbolAddress(&p_ws, g_wsum);
    cudaMemsetAsync(p_deg, 0, sizeof(int) * MM * NN, 0);        // launch 1
    cudaMemsetAsync(p_ws, 0, sizeof(float) * MM, 0);            // launch 2

    conv_h_kernel<<<(NPAD * FF / 8 + 255) / 256, 256>>>(h);     // launch 3
    {
        dim3 grid(HD / 32, FF / 32, MM);
        conv_w_kernel<<<grid, dim3(32, 8)>>>(W);                // launch 4
    }

    cudaEventRecord(ev_fork, 0);
    cudaStreamWaitEvent(s2, ev_fork, 0);
    {
        dim3 grid((EE + 255) / 256, MM);
        count_kernel<<<grid, 256, 0, s2>>>(dst);                // launch 5
    }
    {
        dim3 grid((NN + 127) / 128, HD / 128, MM);
        feat_mma_kernel<<<grid, 256, FEAT_SMEM_BYTES>>>(attn_l, attn_r);  // launch 6
    }
    conv_w1t_kernel<<<dim3(HIDN / 32, HD / 32), dim3(32, 8)>>>(sem_W1);
    scan_partial<<<dim3(NB, MM), 256, 0, s2>>>();
    scan_mid<<<MM, 128, 0, s2>>>();
    scan_final<<<dim3(NB, MM), 256, 0, s2>>>();
    {
        dim3 grid((EE + 255) / 256, MM);
        scatter_kernel<<<grid, 256, 0, s2>>>(src, dst);
    }
    cudaEventRecord(ev_join, s2);
    cudaStreamWaitEvent(0, ev_join, 0);

    {
        dim3 grid((NN + 3) / 4, MM);
        agg_kernel<<<grid, 128>>>(bias_g);
    }
    sem_mma_kernel<<<(MM * NN) / 64, 256, SEM_SMEM_BYTES>>>(sem_b1, sem_W2);
    wsum_kernel<<<(MM * NN + 255) / 256, 256>>>();
    beta_kernel<<<1, 1>>>();
    pred_kernel<<<(NN * 32 + 255) / 256, 256>>>(pred_W, pred_b, out);
}

// round 15
// speedup vs baseline: 1.0532x; 1.0532x over previous
#include <cuda_runtime.h>
#include <cuda_bf16.h>
#include <cuda_fp16.h>
#include <cstdint>
#include <math.h>

// Problem constants
constexpr int NN   = 20000;
constexpr int EE   = 320000;
constexpr int FF   = 256;
constexpr int HH   = 8;
constexpr int DD   = 64;
constexpr int HD   = 512;
constexpr int MM   = 2;
constexpr int CC   = 5;
constexpr int HIDN = 128;
constexpr int NB   = 80;
constexpr int NPAD = 20096;   // 157 * 128

// ---------------- device scratch ----------------
__device__ __half g_feat_h[MM][NN][HD];
__device__ __half g_z_h[MM][NN][HD];
__device__ float g_el[MM][NN][HH];
__device__ float g_er[MM][NN][HH];
__device__ int   g_deg[MM][NN];
__device__ int   g_rowptr[MM][NN + 1];
__device__ int   g_cur[MM][NN];
__device__ int   g_csr_src[MM][EE];
__device__ float g_wsum[MM];
__device__ float g_beta[MM];
__device__ int   g_psum[MM][NB];
__device__ int   g_boff[MM][NB];
__device__ __half g_h_hi[NPAD][FF];          // h split: fp16 hi + fp16 residual
__device__ __half g_h_lo[NPAD][FF];
__device__ __half g_Wt_h[MM][HD][FF];        // W transposed [n][k], fp16
__device__ __half g_W1t_h[HIDN][HD];         // sem_W1 transposed [n][k], fp16

// ---------------- helpers ----------------
__device__ __forceinline__ float fast_tanh(float x) {
    float e2 = __expf(2.f * x);
    return __fdividef(e2 - 1.f, e2 + 1.f);
}
__device__ __forceinline__ uint32_t comb2(uint32_t a, uint32_t b, float b0, float b1) {
    float2 fa = __half22float2(*(__half2*)&a);
    float2 fb = __half22float2(*(__half2*)&b);
    __half2 r = __floats2half2_rn(b0 * fa.x + b1 * fb.x, b0 * fa.y + b1 * fb.y);
    return *(uint32_t*)&r;
}
#define MMA_F16(d, a, b) \
    asm volatile( \
        "mma.sync.aligned.m16n8k16.row.col.f32.f16.f16.f32 " \
        "{%0,%1,%2,%3}, {%4,%5,%6,%7}, {%8,%9}, {%0,%1,%2,%3};" \
        : "+f"((d)[0]), "+f"((d)[1]), "+f"((d)[2]), "+f"((d)[3]) \
        : "r"((a)[0]), "r"((a)[1]), "r"((a)[2]), "r"((a)[3]), \
          "r"((b)[0]), "r"((b)[1]))
#define LDSM_X4(r, addr) \
    asm volatile("ldmatrix.sync.aligned.m8n8.x4.shared.b16 {%0,%1,%2,%3}, [%4];" \
        : "=r"((r)[0]), "=r"((r)[1]), "=r"((r)[2]), "=r"((r)[3]) : "r"(addr))
#define CP_ASYNC16(smem_u32, gptr) \
    asm volatile("cp.async.cg.shared.global [%0], [%1], 16;" \
        :: "r"(smem_u32), "l"(gptr) : "memory")
#define CP_COMMIT() asm volatile("cp.async.commit_group;" ::: "memory")
#define CP_WAIT(n)  asm volatile("cp.async.wait_group %0;" :: "n"(n) : "memory")
#define SMEM_U32(v, p) \
    asm("{ .reg .u64 t; cvta.to.shared.u64 t, %1; cvt.u32.u64 %0, t; }" : "=r"(v) : "l"(p))

// ---------------- conversion kernels ----------------
__global__ void conv_h_kernel(const float* __restrict__ h) {
    int idx = blockIdx.x * blockDim.x + threadIdx.x;   // one per 8 elements
    if (idx >= NPAD * FF / 8) return;
    int row = idx >> 5;
    int kk  = (idx & 31) * 8;
    uint4 hi = make_uint4(0, 0, 0, 0), lo = hi;
    if (row < NN) {
        const float* hp = &h[row * FF + kk];
        float4 a = *(const float4*)hp;
        float4 b = *(const float4*)(hp + 4);
        float v[8] = {a.x, a.y, a.z, a.w, b.x, b.y, b.z, b.w};
        __half vh[8], vl[8];
#pragma unroll
        for (int i = 0; i < 8; i++) {
            vh[i] = __float2half_rn(v[i]);
            vl[i] = __float2half_rn(v[i] - __half2float(vh[i]));
        }
        hi.x = *(uint32_t*)&vh[0]; hi.y = *(uint32_t*)&vh[2];
        hi.z = *(uint32_t*)&vh[4]; hi.w = *(uint32_t*)&vh[6];
        lo.x = *(uint32_t*)&vl[0]; lo.y = *(uint32_t*)&vl[2];
        lo.z = *(uint32_t*)&vl[4]; lo.w = *(uint32_t*)&vl[6];
    }
    *(uint4*)&g_h_hi[row][kk] = hi;
    *(uint4*)&g_h_lo[row][kk] = lo;
}

__global__ void conv_w_kernel(const float* __restrict__ W) {
    __shared__ float tile[32][33];
    int mp = blockIdx.z;
    int n0 = blockIdx.x * 32, k0 = blockIdx.y * 32;
    int tx = threadIdx.x, ty = threadIdx.y;  // 32 x 8
#pragma unroll
    for (int j = 0; j < 4; j++)
        tile[ty + j * 8][tx] = W[mp * FF * HD + (k0 + ty + j * 8) * HD + n0 + tx];
    __syncthreads();
#pragma unroll
    for (int j = 0; j < 4; j++) {
        int n = n0 + ty + j * 8, k = k0 + tx;
        g_Wt_h[mp][n][k] = __float2half_rn(tile[tx][ty + j * 8]);
    }
}

__global__ void conv_w1t_kernel(const float* __restrict__ W1) {
    __shared__ float tile[32][33];
    int n0 = blockIdx.x * 32, k0 = blockIdx.y * 32;
    int tx = threadIdx.x, ty = threadIdx.y;
#pragma unroll
    for (int j = 0; j < 4; j++)
        tile[ty + j * 8][tx] = W1[(k0 + ty + j * 8) * HIDN + n0 + tx];
    __syncthreads();
#pragma unroll
    for (int j = 0; j < 4; j++) {
        int n = n0 + ty + j * 8, k = k0 + tx;
        g_W1t_h[n][k] = __float2half_rn(tile[tx][ty + j * 8]);
    }
}

// ---------------- feat GEMM: 128x128 block, fp16 2-product, 2 stages --------
// Stage layout (80 B/row): A_hi 0, A_lo 10240, B_hi 20480. Stage = 30720.
constexpr int STAGE_STRIDE = 30720;
constexpr int FEAT_SMEM_BYTES = 2 * STAGE_STRIDE + 1024;

__global__ void __launch_bounds__(256, 2)
feat_mma_kernel(const float* __restrict__ al, const float* __restrict__ ar) {
    extern __shared__ char smem[];
    float* s_al = (float*)(smem + 2 * STAGE_STRIDE);
    float* s_ar = s_al + 128;
    uint32_t smem_u32;
    SMEM_U32(smem_u32, smem);

    const int t = threadIdx.x, lane = t & 31, wid = t >> 5;
    const int wm = wid & 3, wn = wid >> 2;        // 4(m) x 2(n)
    const int rowBase = blockIdx.x * 128;
    const int colBase = blockIdx.y * 128;          // 2 heads
    const int mp      = blockIdx.z;

    if (t < 128) {
        s_al[t] = al[mp * HD + colBase + t];
        s_ar[t] = ar[mp * HD + colBase + t];
    }

    const int l_in  = lane & 7;
    const int l_t01 = (lane >> 3) & 1;
    const int l_t23 = lane >> 4;
    const uint32_t a_off0 = (uint32_t)(wm * 32 + l_in + l_t01 * 8) * 80 + l_t23 * 16;
    const uint32_t b_off0 = (uint32_t)(wn * 64 + l_in + (lane >> 4) * 8) * 80
                          + ((lane >> 3) & 1) * 16;

    const int st_row = t >> 1;            // 0..127
    const int st_q0  = (t & 1) * 2;       // 0 or 2

    auto cp_stage = [&](int kc, int buf) {
        uint32_t base = smem_u32 + buf * STAGE_STRIDE;
        const int karow = rowBase + st_row;
        const int kbrow = colBase + st_row;
#pragma unroll
        for (int q = 0; q < 2; q++) {
            uint32_t so = (uint32_t)st_row * 80 + (st_q0 + q) * 16;
            int gk = kc * 32 + (st_q0 + q) * 8;
            CP_ASYNC16(base + so,         &g_h_hi[karow][gk]);
            CP_ASYNC16(base + 10240 + so, &g_h_lo[karow][gk]);
            CP_ASYNC16(base + 20480 + so, &g_Wt_h[mp][kbrow][gk]);
        }
    };

    float d[2][8][4] = {};

    cp_stage(0, 0);
    CP_COMMIT();

    for (int kc = 0; kc < 8; kc++) {
        const int cur = kc & 1;
        if (kc < 7) {
            cp_stage(kc + 1, cur ^ 1);
            CP_COMMIT();
            CP_WAIT(1);
        } else {
            CP_WAIT(0);
        }
        __syncthreads();

        const uint32_t bufb = smem_u32 + cur * STAGE_STRIDE;

#pragma unroll
        for (int ks = 0; ks < 2; ks++) {
            const uint32_t kb = (uint32_t)ks * 32;
            uint32_t ah[2][4], alo[2][4], bh_r[4][4];
#pragma unroll
            for (int mi = 0; mi < 2; mi++) {
                uint32_t ao = bufb + a_off0 + (uint32_t)(mi * 16) * 80 + kb;
                LDSM_X4(ah[mi], ao);
                LDSM_X4(alo[mi], ao + 10240);
            }
#pragma unroll
            for (int p = 0; p < 4; p++) {
                uint32_t bo = bufb + 20480 + b_off0 + (uint32_t)(p * 16) * 80 + kb;
                LDSM_X4(bh_r[p], bo);
            }
#pragma unroll
            for (int mi = 0; mi < 2; mi++)
#pragma unroll
                for (int p = 0; p < 4; p++) {
#pragma unroll
                    for (int q = 0; q < 2; q++) {
                        int ni = p * 2 + q;
                        uint32_t bhq[2] = { bh_r[p][q * 2], bh_r[p][q * 2 + 1] };
                        MMA_F16(d[mi][ni], ah[mi], bhq);
                        MMA_F16(d[mi][ni], alo[mi], bhq);
                    }
                }
        }
        __syncthreads();
    }

    // ---- epilogue ----
    const int head = colBase / DD + wn;
#pragma unroll
    for (int mi = 0; mi < 2; mi++) {
#pragma unroll
        for (int half = 0; half < 2; half++) {
            int r = wm * 32 + mi * 16 + half * 8 + (lane >> 2);
            int grow = rowBase + r;
            float el = 0.f, er = 0.f;
#pragma unroll
            for (int ni = 0; ni < 8; ni++) {
                float v0 = d[mi][ni][half * 2 + 0];
                float v1 = d[mi][ni][half * 2 + 1];
                int c = wn * 64 + ni * 8 + (lane & 3) * 2;
                el += v0 * s_al[c] + v1 * s_al[c + 1];
                er += v0 * s_ar[c] + v1 * s_ar[c + 1];
                if (grow < NN) {
                    __half2 hv = __floats2half2_rn(v0, v1);
                    *(__half2*)&g_feat_h[mp][grow][colBase + c] = hv;
                }
            }
            el += __shfl_xor_sync(0xffffffffu, el, 1);
            el += __shfl_xor_sync(0xffffffffu, el, 2);
            er += __shfl_xor_sync(0xffffffffu, er, 1);
            er += __shfl_xor_sync(0xffffffffu, er, 2);
            if ((lane & 3) == 0 && grow < NN) {
                g_el[mp][grow][head] = el;
                g_er[mp][grow][head] = er;
            }
        }
    }
}

// ---------------- CSR build ----------------
__global__ void count_kernel(const int* __restrict__ dst) {
    int mp = blockIdx.y;
    int e = blockIdx.x * blockDim.x + threadIdx.x;
    if (e < EE) atomicAdd(&g_deg[mp][dst[mp * EE + e]], 1);
}

__global__ void scan_partial() {
    int mp = blockIdx.y;
    int i = blockIdx.x * 256 + threadIdx.x;
    int v = (i < NN) ? g_deg[mp][i] : 0;
#pragma unroll
    for (int off = 16; off; off >>= 1) v += __shfl_xor_sync(0xffffffffu, v, off);
    __shared__ int ws[8];
    if ((threadIdx.x & 31) == 0) ws[threadIdx.x >> 5] = v;
    __syncthreads();
    if (threadIdx.x == 0) {
        int s = 0;
#pragma unroll
        for (int w = 0; w < 8; w++) s += ws[w];
        g_psum[mp][blockIdx.x] = s;
    }
}

__global__ void scan_mid() {
    int mp = blockIdx.x;
    int t = threadIdx.x, lane = t & 31, wid = t >> 5;
    int v = (t < NB) ? g_psum[mp][t] : 0;
    int x = v;
#pragma unroll
    for (int off = 1; off < 32; off <<= 1) {
        int y = __shfl_up_sync(0xffffffffu, x, off);
        if (lane >= off) x += y;
    }
    __shared__ int ws[4];
    if (lane == 31) ws[wid] = x;
    __syncthreads();
    int woff = 0;
    for (int w = 0; w < wid; w++) woff += ws[w];
    if (t < NB) g_boff[mp][t] = woff + x - v;
}

__global__ void scan_final() {
    int mp = blockIdx.y;
    int t = threadIdx.x, lane = t & 31, wid = t >> 5;
    int i = blockIdx.x * 256 + t;
    int v = (i < NN) ? g_deg[mp][i] : 0;
    int x = v;
#pragma unroll
    for (int off = 1; off < 32; off <<= 1) {
        int y = __shfl_up_sync(0xffffffffu, x, off);
        if (lane >= off) x += y;
    }
    __shared__ int ws[8];
    if (lane == 31) ws[wid] = x;
    __syncthreads();
    int woff = 0;
    for (int w = 0; w < wid; w++) woff += ws[w];
    int excl = g_boff[mp][blockIdx.x] + woff + x - v;
    if (i < NN) {
        g_rowptr[mp][i] = excl;
        g_cur[mp][i]    = excl;
        if (i == NN - 1) g_rowptr[mp][NN] = excl + v;
    }
}

__global__ void scatter_kernel(const int* __restrict__ src,
                               const int* __restrict__ dst) {
    int mp = blockIdx.y;
    int e = blockIdx.x * blockDim.x + threadIdx.x;
    if (e < EE) {
        int d = dst[mp * EE + e];
        int pos = atomicAdd(&g_cur[mp][d], 1);
        g_csr_src[mp][pos] = src[mp * EE + e];
    }
}

// ---------------- edge softmax + aggregation (block per node, fp16 feat) ----
__global__ void agg_kernel(const float* __restrict__ bias) {
    const int v  = blockIdx.x;
    const int mp = blockIdx.y;
    const int t  = threadIdx.x;  // 128

    __shared__ float ser[HH], sden[HH];
    __shared__ float sex[16][HH];
    __shared__ int   ssrc[16];

    const int start = g_rowptr[mp][v];
    const int deg   = g_rowptr[mp][v + 1] - start;

    if (t < HH) {
        ser[t]  = g_er[mp][v][t];
        sden[t] = 0.f;
    }
    __syncthreads();

    float acc0 = 0.f, acc1 = 0.f, acc2 = 0.f, acc3 = 0.f;
    const int d0  = t * 4;
    const int myh = t >> 4;

    for (int base = 0; base < deg; base += 16) {
        int cn = min(16, deg - base);
        if (t < cn * 8) {
            int i = t >> 3, hh = t & 7;
            int s = g_csr_src[mp][start + base + i];
            if (hh == 0) ssrc[i] = s;
            float e = g_el[mp][s][hh] + ser[hh];
            e = (e > 0.f) ? e : 0.2f * e;
            sex[i][hh] = __expf(e);
        }
        __syncthreads();
        if (t < 8) {
            float dsum = 0.f;
            for (int i = 0; i < cn; i++) dsum += sex[i][t];
            sden[t] += dsum;
        }
#pragma unroll 4
        for (int i = 0; i < cn; i++) {
            int s = ssrc[i];
            float w = sex[i][myh];
            uint2 raw = *(const uint2*)&g_feat_h[mp][s][d0];
            float2 f01 = __half22float2(*(__half2*)&raw.x);
            float2 f23 = __half22float2(*(__half2*)&raw.y);
            acc0 += w * f01.x;
            acc1 += w * f01.y;
            acc2 += w * f23.x;
            acc3 += w * f23.y;
        }
        __syncthreads();
    }

    float inv = 1.f / fmaxf(sden[myh], 1e-9f);
    const float* b = bias + mp * HD + d0;
    float o0 = acc0 * inv + b[0];
    float o1 = acc1 * inv + b[1];
    float o2 = acc2 * inv + b[2];
    float o3 = acc3 * inv + b[3];
    o0 = (o0 > 0.f) ? o0 : (__expf(o0) - 1.f);
    o1 = (o1 > 0.f) ? o1 : (__expf(o1) - 1.f);
    o2 = (o2 > 0.f) ? o2 : (__expf(o2) - 1.f);
    o3 = (o3 > 0.f) ? o3 : (__expf(o3) - 1.f);
    uint2 zout;
    *(__half2*)&zout.x = __floats2half2_rn(o0, o1);
    *(__half2*)&zout.y = __floats2half2_rn(o2, o3);
    *(uint2*)&g_z_h[mp][v][d0] = zout;
}

// ---------------- semantic attention: fp16 MMA, pipelined, fused wsum -------
// Block 64 rows x 128 cols, K=512 in 16 chunks of 32. Warps 2(m) x 4(n).
// Stage: A 64*80=5120, B 128*80=10240 -> 15360; double-buffered.
constexpr int SEM_STAGE = 15360;
constexpr int SEM_SMEM_BYTES = 2 * SEM_STAGE + 1536;

__global__ void __launch_bounds__(256, 2)
sem_mma_kernel(const float* __restrict__ b1, const float* __restrict__ W2) {
    extern __shared__ char smem[];
    float* s_b1 = (float*)(smem + 2 * SEM_STAGE);
    float* s_w2 = s_b1 + 128;
    float* s_wr = s_w2 + 128;   // 64
    uint32_t smem_u32;
    SMEM_U32(smem_u32, smem);

    const int t = threadIdx.x, lane = t & 31, wid = t >> 5;
    const int wm = wid & 1, wn = wid >> 1;
    const int rowBase = blockIdx.x * 64;
    const __half* Zh = &g_z_h[0][0][0];   // [40000][512]

    if (t < 128) { s_b1[t] = b1[t]; s_w2[t] = W2[t]; }
    if (t < 64) s_wr[t] = 0.f;

    const int l_in  = lane & 7;
    const int l_t01 = (lane >> 3) & 1;
    const int l_t23 = lane >> 4;
    const uint32_t a_off0 = (uint32_t)(wm * 32 + l_in + l_t01 * 8) * 80 + l_t23 * 16;
    const uint32_t b_off0 = 5120u + (uint32_t)(wn * 32 + l_in + (lane >> 4) * 8) * 80
                          + ((lane >> 3) & 1) * 16;

    // staging: A = 64 rows x 4 chunks (256 transfers), B = 128 rows x 4 (512)
    auto cp_stage = [&](int kc, int buf) {
        uint32_t base = smem_u32 + buf * SEM_STAGE;
        {
            int row = t >> 2, q = t & 3;
            CP_ASYNC16(base + (uint32_t)row * 80 + q * 16,
                       Zh + (rowBase + row) * HD + kc * 32 + q * 8);
        }
#pragma unroll
        for (int j = 0; j < 2; j++) {
            int idx = t + j * 256;
            int row = idx >> 2, q = idx & 3;
            CP_ASYNC16(base + 5120 + (uint32_t)row * 80 + q * 16,
                       &g_W1t_h[row][kc * 32 + q * 8]);
        }
    };

    float d[2][4][4] = {};

    cp_stage(0, 0);
    CP_COMMIT();

    for (int kc = 0; kc < 16; kc++) {
        const int cur = kc & 1;
        if (kc < 15) {
            cp_stage(kc + 1, cur ^ 1);
            CP_COMMIT();
            CP_WAIT(1);
        } else {
            CP_WAIT(0);
        }
        __syncthreads();

        const uint32_t bufb = smem_u32 + cur * SEM_STAGE;
#pragma unroll
        for (int ks = 0; ks < 2; ks++) {
            const uint32_t kb = (uint32_t)ks * 32;
            uint32_t ah[2][4], bh[2][4];
#pragma unroll
            for (int mi = 0; mi < 2; mi++)
                LDSM_X4(ah[mi], bufb + a_off0 + (uint32_t)(mi * 16) * 80 + kb);
#pragma unroll
            for (int p = 0; p < 2; p++)
                LDSM_X4(bh[p], bufb + b_off0 + (uint32_t)(p * 16) * 80 + kb);
#pragma unroll
            for (int mi = 0; mi < 2; mi++)
#pragma unroll
                for (int p = 0; p < 2; p++)
#pragma unroll
                    for (int q = 0; q < 2; q++) {
                        int ni = p * 2 + q;
                        uint32_t bq[2] = { bh[p][q * 2], bh[p][q * 2 + 1] };
                        MMA_F16(d[mi][ni], ah[mi], bq);
                    }
        }
        __syncthreads();
    }

    // epilogue: w[row] = sum_c tanh(acc + b1[c]) * W2[c]; fused wsum
#pragma unroll
    for (int mi = 0; mi < 2; mi++) {
#pragma unroll
        for (int half = 0; half < 2; half++) {
            float p = 0.f;
#pragma unroll
            for (int ni = 0; ni < 4; ni++) {
                int c = wn * 32 + ni * 8 + (lane & 3) * 2;
                p += fast_tanh(d[mi][ni][half * 2 + 0] + s_b1[c]) * s_w2[c];
                p += fast_tanh(d[mi][ni][half * 2 + 1] + s_b1[c + 1]) * s_w2[c + 1];
            }
            p += __shfl_xor_sync(0xffffffffu, p, 1);
            p += __shfl_xor_sync(0xffffffffu, p, 2);
            if ((lane & 3) == 0)
                atomicAdd(&s_wr[wm * 32 + mi * 16 + half * 8 + (lane >> 2)], p);
        }
    }
    __syncthreads();
    if (t < 64) {
        float v = s_wr[t];
        int grow = rowBase + t;
        float v0 = (grow < NN) ? v : 0.f;
        float v1 = (grow >= NN) ? v : 0.f;
#pragma unroll
        for (int off = 16; off; off >>= 1) {
            v0 += __shfl_xor_sync(0xffffffffu, v0, off);
            v1 += __shfl_xor_sync(0xffffffffu, v1, off);
        }
        if (lane == 0) {
            atomicAdd(&g_wsum[0], v0);
            atomicAdd(&g_wsum[1], v1);
        }
    }
}

__global__ void beta_kernel() {
    float a = g_wsum[0] / (float)NN;
    float b = g_wsum[1] / (float)NN;
    float m = fmaxf(a, b);
    float ea = __expf(a - m), eb = __expf(b - m);
    float s = ea + eb;
    g_beta[0] = ea / s;
    g_beta[1] = eb / s;
}

// ---------------- prediction via fp16 MMA -----------------------------------
// Block 256 rows, 8 warps (32 rows each), K=512 in 16 chunks of 32, N=8 (5 used)
constexpr int PRED_SMEM_BYTES = 256 * 80;

__global__ void __launch_bounds__(256)
pred_mma_kernel(const float* __restrict__ pw, const float* __restrict__ pb,
                float* __restrict__ out) {
    extern __shared__ char smem[];
    uint32_t smem_u32;
    SMEM_U32(smem_u32, smem);

    const int t = threadIdx.x, lane = t & 31, wid = t >> 5;
    const int rowBase = blockIdx.x * 256;
    const float b0 = g_beta[0], b1 = g_beta[1];

    const int l_in  = lane & 7;
    const int l_t01 = (lane >> 3) & 1;
    const int l_t23 = lane >> 4;
    const uint32_t a_off0 = (uint32_t)(wid * 32 + l_in + l_t01 * 8) * 80 + l_t23 * 16;

    const int n_col = lane >> 2;          // 0..7 (valid < CC)
    const bool nval = n_col < CC;

    float d[2][4] = {};

    for (int kc = 0; kc < 16; kc++) {
        // stage: thread t owns row t, 32 k elems (4 uint4 per z array)
        {
            int grow = rowBase + t;
            uint4 o[4];
            if (grow < NN) {
                const uint4* z0p = (const uint4*)&g_z_h[0][grow][kc * 32];
                const uint4* z1p = (const uint4*)&g_z_h[1][grow][kc * 32];
#pragma unroll
                for (int w = 0; w < 4; w++) {
                    uint4 za = z0p[w], zb = z1p[w];
                    o[w].x = comb2(za.x, zb.x, b0, b1);
                    o[w].y = comb2(za.y, zb.y, b0, b1);
                    o[w].z = comb2(za.z, zb.z, b0, b1);
                    o[w].w = comb2(za.w, zb.w, b0, b1);
                }
            } else {
#pragma unroll
                for (int w = 0; w < 4; w++) o[w] = make_uint4(0, 0, 0, 0);
            }
            char* dstp = smem + t * 80;
#pragma unroll
            for (int w = 0; w < 4; w++) *(uint4*)(dstp + w * 16) = o[w];
        }
        __syncthreads();

#pragma unroll
        for (int ks = 0; ks < 2; ks++) {
            uint32_t a0[4], a1[4];
            LDSM_X4(a0, smem_u32 + a_off0 + (uint32_t)ks * 32);
            LDSM_X4(a1, smem_u32 + a_off0 + 16u * 80 + (uint32_t)ks * 32);
            int kk = kc * 32 + ks * 16 + (lane & 3) * 2;
            uint32_t br[2] = {0, 0};
            if (nval) {
                __half2 q0 = __floats2half2_rn(pw[kk * CC + n_col], pw[(kk + 1) * CC + n_col]);
                __half2 q1 = __floats2half2_rn(pw[(kk + 8) * CC + n_col], pw[(kk + 9) * CC + n_col]);
                br[0] = *(uint32_t*)&q0;
                br[1] = *(uint32_t*)&q1;
            }
            MMA_F16(d[0], a0, br);
            MMA_F16(d[1], a1, br);
        }
        __syncthreads();
    }

    // epilogue
#pragma unroll
    for (int mi = 0; mi < 2; mi++) {
#pragma unroll
        for (int half = 0; half < 2; half++) {
            int grow = rowBase + wid * 32 + mi * 16 + half * 8 + (lane >> 2);
            int c0 = (lane & 3) * 2;
            if (grow < NN) {
                if (c0 < CC)     out[grow * CC + c0]     = d[mi][half * 2 + 0] + pb[c0];
                if (c0 + 1 < CC) out[grow * CC + c0 + 1] = d[mi][half * 2 + 1] + pb[c0 + 1];
            }
        }
    }
}

// ---------------- launch ----------------
extern "C" void kernel_launch(void* const* d_in, const int* in_sizes, int n_in,
                              void* d_out, int out_size) {
    const float* h      = (const float*)d_in[0];
    const int*   src    = (const int*)d_in[1];
    const int*   dst    = (const int*)d_in[2];
    const float* W      = (const float*)d_in[3];
    const float* attn_l = (const float*)d_in[4];
    const float* attn_r = (const float*)d_in[5];
    const float* bias_g = (const float*)d_in[6];
    const float* sem_W1 = (const float*)d_in[7];
    const float* sem_b1 = (const float*)d_in[8];
    const float* sem_W2 = (const float*)d_in[9];
    const float* pred_W = (const float*)d_in[10];
    const float* pred_b = (const float*)d_in[11];
    float* out = (float*)d_out;

    static cudaStream_t s2 = nullptr;
    static cudaEvent_t ev_fork = nullptr, ev_join = nullptr;
    if (s2 == nullptr) {
        cudaStreamCreateWithFlags(&s2, cudaStreamNonBlocking);
        cudaEventCreateWithFlags(&ev_fork, cudaEventDisableTiming);
        cudaEventCreateWithFlags(&ev_join, cudaEventDisableTiming);
    }

    cudaFuncSetAttribute(feat_mma_kernel,
                         cudaFuncAttributeMaxDynamicSharedMemorySize, FEAT_SMEM_BYTES);
    cudaFuncSetAttribute(sem_mma_kernel,
                         cudaFuncAttributeMaxDynamicSharedMemorySize, SEM_SMEM_BYTES);
    cudaFuncSetAttribute(pred_mma_kernel,
                         cudaFuncAttributeMaxDynamicSharedMemorySize, PRED_SMEM_BYTES);

    void* p_deg = nullptr;
    void* p_ws  = nullptr;
    cudaGetSymbolAddress(&p_deg, g_deg);
    cudaGetSymbolAddress(&p_ws, g_wsum);
    cudaMemsetAsync(p_deg, 0, sizeof(int) * MM * NN, 0);        // launch 1
    cudaMemsetAsync(p_ws, 0, sizeof(float) * MM, 0);            // launch 2

    conv_h_kernel<<<(NPAD * FF / 8 + 255) / 256, 256>>>(h);     // launch 3
    {
        dim3 grid(HD / 32, FF / 32, MM);
        conv_w_kernel<<<grid, dim3(32, 8)>>>(W);                // launch 4
    }

    cudaEventRecord(ev_fork, 0);
    cudaStreamWaitEvent(s2, ev_fork, 0);
    {
        dim3 grid((EE + 255) / 256, MM);
        count_kernel<<<grid, 256, 0, s2>>>(dst);                // launch 5
    }
    {
        dim3 grid((NN + 127) / 128, HD / 128, MM);
        feat_mma_kernel<<<grid, 256, FEAT_SMEM_BYTES>>>(attn_l, attn_r);  // launch 6
    }
    conv_w1t_kernel<<<dim3(HIDN / 32, HD / 32), dim3(32, 8)>>>(sem_W1);
    scan_partial<<<dim3(NB, MM), 256, 0, s2>>>();
    scan_mid<<<MM, 128, 0, s2>>>();
    scan_final<<<dim3(NB, MM), 256, 0, s2>>>();
    {
        dim3 grid((EE + 255) / 256, MM);
        scatter_kernel<<<grid, 256, 0, s2>>>(src, dst);
    }
    cudaEventRecord(ev_join, s2);
    cudaStreamWaitEvent(0, ev_join, 0);

    {
        dim3 grid(NN, MM);
        agg_kernel<<<grid, 128>>>(bias_g);
    }
    sem_mma_kernel<<<(MM * NN) / 64, 256, SEM_SMEM_BYTES>>>(sem_b1, sem_W2);
    beta_kernel<<<1, 1>>>();
    pred_mma_kernel<<<(NN + 255) / 256, 256, PRED_SMEM_BYTES>>>(pred_W, pred_b, out);
}

// round 16
// speedup vs baseline: 1.2089x; 1.1478x over previous
#include <cuda_runtime.h>
#include <cuda_bf16.h>
#include <cuda_fp16.h>
#include <cstdint>
#include <math.h>

// Problem constants
constexpr int NN   = 20000;
constexpr int EE   = 320000;
constexpr int FF   = 256;
constexpr int HH   = 8;
constexpr int DD   = 64;
constexpr int HD   = 512;
constexpr int MM   = 2;
constexpr int CC   = 5;
constexpr int HIDN = 128;
constexpr int NB   = 80;
constexpr int NPAD = 20096;   // 157 * 128

// ---------------- device scratch ----------------
__device__ __half g_feat_h[MM][NN][HD];
__device__ __half g_z_h[MM][NN][HD];
__device__ float g_el[MM][NN][HH];
__device__ float g_er[MM][NN][HH];
__device__ int   g_deg[MM][NN];
__device__ int   g_rowptr[MM][NN + 1];
__device__ int   g_cur[MM][NN];
__device__ int   g_csr_src[MM][EE];
__device__ float g_wsum[MM];
__device__ float g_beta[MM];
__device__ int   g_psum[MM][NB];
__device__ int   g_boff[MM][NB];
__device__ __half g_h_h[NPAD][FF];           // h, fp16
__device__ __half g_Wt_h[MM][HD][FF];        // W transposed [n][k], fp16
__device__ __half g_W1t_h[HIDN][HD];         // sem_W1 transposed [n][k], fp16

// ---------------- helpers ----------------
__device__ __forceinline__ float fast_tanh(float x) {
    float e2 = __expf(2.f * x);
    return __fdividef(e2 - 1.f, e2 + 1.f);
}
__device__ __forceinline__ uint32_t comb2(uint32_t a, uint32_t b, float b0, float b1) {
    float2 fa = __half22float2(*(__half2*)&a);
    float2 fb = __half22float2(*(__half2*)&b);
    __half2 r = __floats2half2_rn(b0 * fa.x + b1 * fb.x, b0 * fa.y + b1 * fb.y);
    return *(uint32_t*)&r;
}
#define MMA_F16(d, a, b) \
    asm volatile( \
        "mma.sync.aligned.m16n8k16.row.col.f32.f16.f16.f32 " \
        "{%0,%1,%2,%3}, {%4,%5,%6,%7}, {%8,%9}, {%0,%1,%2,%3};" \
        : "+f"((d)[0]), "+f"((d)[1]), "+f"((d)[2]), "+f"((d)[3]) \
        : "r"((a)[0]), "r"((a)[1]), "r"((a)[2]), "r"((a)[3]), \
          "r"((b)[0]), "r"((b)[1]))
#define LDSM_X4(r, addr) \
    asm volatile("ldmatrix.sync.aligned.m8n8.x4.shared.b16 {%0,%1,%2,%3}, [%4];" \
        : "=r"((r)[0]), "=r"((r)[1]), "=r"((r)[2]), "=r"((r)[3]) : "r"(addr))
#define CP_ASYNC16(smem_u32, gptr) \
    asm volatile("cp.async.cg.shared.global [%0], [%1], 16;" \
        :: "r"(smem_u32), "l"(gptr) : "memory")
#define CP_COMMIT() asm volatile("cp.async.commit_group;" ::: "memory")
#define CP_WAIT(n)  asm volatile("cp.async.wait_group %0;" :: "n"(n) : "memory")
#define SMEM_U32(v, p) \
    asm("{ .reg .u64 t; cvta.to.shared.u64 t, %1; cvt.u32.u64 %0, t; }" : "=r"(v) : "l"(p))

// ---------------- conversion kernels ----------------
__global__ void conv_h_kernel(const float* __restrict__ h) {
    int idx = blockIdx.x * blockDim.x + threadIdx.x;   // one per 8 elements
    if (idx >= NPAD * FF / 8) return;
    int row = idx >> 5;
    int kk  = (idx & 31) * 8;
    uint4 hi = make_uint4(0, 0, 0, 0);
    if (row < NN) {
        const float* hp = &h[row * FF + kk];
        float4 a = *(const float4*)hp;
        float4 b = *(const float4*)(hp + 4);
        __half2 h0 = __floats2half2_rn(a.x, a.y);
        __half2 h1 = __floats2half2_rn(a.z, a.w);
        __half2 h2 = __floats2half2_rn(b.x, b.y);
        __half2 h3 = __floats2half2_rn(b.z, b.w);
        hi.x = *(uint32_t*)&h0; hi.y = *(uint32_t*)&h1;
        hi.z = *(uint32_t*)&h2; hi.w = *(uint32_t*)&h3;
    }
    *(uint4*)&g_h_h[row][kk] = hi;
}

__global__ void conv_w_kernel(const float* __restrict__ W) {
    __shared__ float tile[32][33];
    int mp = blockIdx.z;
    int n0 = blockIdx.x * 32, k0 = blockIdx.y * 32;
    int tx = threadIdx.x, ty = threadIdx.y;  // 32 x 8
#pragma unroll
    for (int j = 0; j < 4; j++)
        tile[ty + j * 8][tx] = W[mp * FF * HD + (k0 + ty + j * 8) * HD + n0 + tx];
    __syncthreads();
#pragma unroll
    for (int j = 0; j < 4; j++) {
        int n = n0 + ty + j * 8, k = k0 + tx;
        g_Wt_h[mp][n][k] = __float2half_rn(tile[tx][ty + j * 8]);
    }
}

__global__ void conv_w1t_kernel(const float* __restrict__ W1) {
    __shared__ float tile[32][33];
    int n0 = blockIdx.x * 32, k0 = blockIdx.y * 32;
    int tx = threadIdx.x, ty = threadIdx.y;
#pragma unroll
    for (int j = 0; j < 4; j++)
        tile[ty + j * 8][tx] = W1[(k0 + ty + j * 8) * HIDN + n0 + tx];
    __syncthreads();
#pragma unroll
    for (int j = 0; j < 4; j++) {
        int n = n0 + ty + j * 8, k = k0 + tx;
        g_W1t_h[n][k] = __float2half_rn(tile[tx][ty + j * 8]);
    }
}

// ---------------- feat GEMM: 128x128 block, fp16 single product, 2 stages ---
// Stage layout (80 B/row): A 0 (10240), B 10240 (10240). Stage = 20480.
constexpr int STAGE_STRIDE = 20480;
constexpr int FEAT_SMEM_BYTES = 2 * STAGE_STRIDE + 1024;

__global__ void __launch_bounds__(256, 2)
feat_mma_kernel(const float* __restrict__ al, const float* __restrict__ ar) {
    extern __shared__ char smem[];
    float* s_al = (float*)(smem + 2 * STAGE_STRIDE);
    float* s_ar = s_al + 128;
    uint32_t smem_u32;
    SMEM_U32(smem_u32, smem);

    const int t = threadIdx.x, lane = t & 31, wid = t >> 5;
    const int wm = wid & 3, wn = wid >> 2;        // 4(m) x 2(n)
    const int rowBase = blockIdx.x * 128;
    const int colBase = blockIdx.y * 128;          // 2 heads
    const int mp      = blockIdx.z;

    if (t < 128) {
        s_al[t] = al[mp * HD + colBase + t];
        s_ar[t] = ar[mp * HD + colBase + t];
    }

    const int l_in  = lane & 7;
    const int l_t01 = (lane >> 3) & 1;
    const int l_t23 = lane >> 4;
    const uint32_t a_off0 = (uint32_t)(wm * 32 + l_in + l_t01 * 8) * 80 + l_t23 * 16;
    const uint32_t b_off0 = 10240u + (uint32_t)(wn * 64 + l_in + (lane >> 4) * 8) * 80
                          + ((lane >> 3) & 1) * 16;

    const int st_row = t >> 1;            // 0..127
    const int st_q0  = (t & 1) * 2;       // 0 or 2

    auto cp_stage = [&](int kc, int buf) {
        uint32_t base = smem_u32 + buf * STAGE_STRIDE;
        const int karow = rowBase + st_row;
        const int kbrow = colBase + st_row;
#pragma unroll
        for (int q = 0; q < 2; q++) {
            uint32_t so = (uint32_t)st_row * 80 + (st_q0 + q) * 16;
            int gk = kc * 32 + (st_q0 + q) * 8;
            CP_ASYNC16(base + so,          &g_h_h[karow][gk]);
            CP_ASYNC16(base + 10240 + so,  &g_Wt_h[mp][kbrow][gk]);
        }
    };

    float d[2][8][4] = {};

    cp_stage(0, 0);
    CP_COMMIT();

    for (int kc = 0; kc < 8; kc++) {
        const int cur = kc & 1;
        if (kc < 7) {
            cp_stage(kc + 1, cur ^ 1);
            CP_COMMIT();
            CP_WAIT(1);
        } else {
            CP_WAIT(0);
        }
        __syncthreads();

        const uint32_t bufb = smem_u32 + cur * STAGE_STRIDE;

#pragma unroll
        for (int ks = 0; ks < 2; ks++) {
            const uint32_t kb = (uint32_t)ks * 32;
            uint32_t ah[2][4], bh_r[4][4];
#pragma unroll
            for (int mi = 0; mi < 2; mi++)
                LDSM_X4(ah[mi], bufb + a_off0 + (uint32_t)(mi * 16) * 80 + kb);
#pragma unroll
            for (int p = 0; p < 4; p++)
                LDSM_X4(bh_r[p], bufb + b_off0 + (uint32_t)(p * 16) * 80 + kb);
#pragma unroll
            for (int mi = 0; mi < 2; mi++)
#pragma unroll
                for (int p = 0; p < 4; p++) {
#pragma unroll
                    for (int q = 0; q < 2; q++) {
                        int ni = p * 2 + q;
                        uint32_t bhq[2] = { bh_r[p][q * 2], bh_r[p][q * 2 + 1] };
                        MMA_F16(d[mi][ni], ah[mi], bhq);
                    }
                }
        }
        __syncthreads();
    }

    // ---- epilogue ----
    const int head = colBase / DD + wn;
#pragma unroll
    for (int mi = 0; mi < 2; mi++) {
#pragma unroll
        for (int half = 0; half < 2; half++) {
            int r = wm * 32 + mi * 16 + half * 8 + (lane >> 2);
            int grow = rowBase + r;
            float el = 0.f, er = 0.f;
#pragma unroll
            for (int ni = 0; ni < 8; ni++) {
                float v0 = d[mi][ni][half * 2 + 0];
                float v1 = d[mi][ni][half * 2 + 1];
                int c = wn * 64 + ni * 8 + (lane & 3) * 2;
                el += v0 * s_al[c] + v1 * s_al[c + 1];
                er += v0 * s_ar[c] + v1 * s_ar[c + 1];
                if (grow < NN) {
                    __half2 hv = __floats2half2_rn(v0, v1);
                    *(__half2*)&g_feat_h[mp][grow][colBase + c] = hv;
                }
            }
            el += __shfl_xor_sync(0xffffffffu, el, 1);
            el += __shfl_xor_sync(0xffffffffu, el, 2);
            er += __shfl_xor_sync(0xffffffffu, er, 1);
            er += __shfl_xor_sync(0xffffffffu, er, 2);
            if ((lane & 3) == 0 && grow < NN) {
                g_el[mp][grow][head] = el;
                g_er[mp][grow][head] = er;
            }
        }
    }
}

// ---------------- CSR build ----------------
__global__ void count_kernel(const int* __restrict__ dst) {
    int mp = blockIdx.y;
    int e = blockIdx.x * blockDim.x + threadIdx.x;
    if (e < EE) atomicAdd(&g_deg[mp][dst[mp * EE + e]], 1);
}

__global__ void scan_partial() {
    int mp = blockIdx.y;
    int i = blockIdx.x * 256 + threadIdx.x;
    int v = (i < NN) ? g_deg[mp][i] : 0;
#pragma unroll
    for (int off = 16; off; off >>= 1) v += __shfl_xor_sync(0xffffffffu, v, off);
    __shared__ int ws[8];
    if ((threadIdx.x & 31) == 0) ws[threadIdx.x >> 5] = v;
    __syncthreads();
    if (threadIdx.x == 0) {
        int s = 0;
#pragma unroll
        for (int w = 0; w < 8; w++) s += ws[w];
        g_psum[mp][blockIdx.x] = s;
    }
}

__global__ void scan_mid() {
    int mp = blockIdx.x;
    int t = threadIdx.x, lane = t & 31, wid = t >> 5;
    int v = (t < NB) ? g_psum[mp][t] : 0;
    int x = v;
#pragma unroll
    for (int off = 1; off < 32; off <<= 1) {
        int y = __shfl_up_sync(0xffffffffu, x, off);
        if (lane >= off) x += y;
    }
    __shared__ int ws[4];
    if (lane == 31) ws[wid] = x;
    __syncthreads();
    int woff = 0;
    for (int w = 0; w < wid; w++) woff += ws[w];
    if (t < NB) g_boff[mp][t] = woff + x - v;
}

__global__ void scan_final() {
    int mp = blockIdx.y;
    int t = threadIdx.x, lane = t & 31, wid = t >> 5;
    int i = blockIdx.x * 256 + t;
    int v = (i < NN) ? g_deg[mp][i] : 0;
    int x = v;
#pragma unroll
    for (int off = 1; off < 32; off <<= 1) {
        int y = __shfl_up_sync(0xffffffffu, x, off);
        if (lane >= off) x += y;
    }
    __shared__ int ws[8];
    if (lane == 31) ws[wid] = x;
    __syncthreads();
    int woff = 0;
    for (int w = 0; w < wid; w++) woff += ws[w];
    int excl = g_boff[mp][blockIdx.x] + woff + x - v;
    if (i < NN) {
        g_rowptr[mp][i] = excl;
        g_cur[mp][i]    = excl;
        if (i == NN - 1) g_rowptr[mp][NN] = excl + v;
    }
}

__global__ void scatter_kernel(const int* __restrict__ src,
                               const int* __restrict__ dst) {
    int mp = blockIdx.y;
    int e = blockIdx.x * blockDim.x + threadIdx.x;
    if (e < EE) {
        int d = dst[mp * EE + e];
        int pos = atomicAdd(&g_cur[mp][d], 1);
        g_csr_src[mp][pos] = src[mp * EE + e];
    }
}

// ---------------- edge softmax + aggregation (block per node, fp16 feat) ----
__global__ void agg_kernel(const float* __restrict__ bias) {
    const int v  = blockIdx.x;
    const int mp = blockIdx.y;
    const int t  = threadIdx.x;  // 128

    __shared__ float ser[HH], sden[HH];
    __shared__ float sex[16][HH];
    __shared__ int   ssrc[16];

    const int start = g_rowptr[mp][v];
    const int deg   = g_rowptr[mp][v + 1] - start;

    if (t < HH) {
        ser[t]  = g_er[mp][v][t];
        sden[t] = 0.f;
    }
    __syncthreads();

    float acc0 = 0.f, acc1 = 0.f, acc2 = 0.f, acc3 = 0.f;
    const int d0  = t * 4;
    const int myh = t >> 4;

    for (int base = 0; base < deg; base += 16) {
        int cn = min(16, deg - base);
        if (t < cn * 8) {
            int i = t >> 3, hh = t & 7;
            int s = g_csr_src[mp][start + base + i];
            if (hh == 0) ssrc[i] = s;
            float e = g_el[mp][s][hh] + ser[hh];
            e = (e > 0.f) ? e : 0.2f * e;
            sex[i][hh] = __expf(e);
        }
        __syncthreads();
        if (t < 8) {
            float dsum = 0.f;
            for (int i = 0; i < cn; i++) dsum += sex[i][t];
            sden[t] += dsum;
        }
#pragma unroll 4
        for (int i = 0; i < cn; i++) {
            int s = ssrc[i];
            float w = sex[i][myh];
            uint2 raw = *(const uint2*)&g_feat_h[mp][s][d0];
            float2 f01 = __half22float2(*(__half2*)&raw.x);
            float2 f23 = __half22float2(*(__half2*)&raw.y);
            acc0 += w * f01.x;
            acc1 += w * f01.y;
            acc2 += w * f23.x;
            acc3 += w * f23.y;
        }
        __syncthreads();
    }

    float inv = 1.f / fmaxf(sden[myh], 1e-9f);
    const float* b = bias + mp * HD + d0;
    float o0 = acc0 * inv + b[0];
    float o1 = acc1 * inv + b[1];
    float o2 = acc2 * inv + b[2];
    float o3 = acc3 * inv + b[3];
    o0 = (o0 > 0.f) ? o0 : (__expf(o0) - 1.f);
    o1 = (o1 > 0.f) ? o1 : (__expf(o1) - 1.f);
    o2 = (o2 > 0.f) ? o2 : (__expf(o2) - 1.f);
    o3 = (o3 > 0.f) ? o3 : (__expf(o3) - 1.f);
    uint2 zout;
    *(__half2*)&zout.x = __floats2half2_rn(o0, o1);
    *(__half2*)&zout.y = __floats2half2_rn(o2, o3);
    *(uint2*)&g_z_h[mp][v][d0] = zout;
}

// ---------------- semantic attention: fp16 MMA, pipelined, fused wsum -------
constexpr int SEM_STAGE = 15360;
constexpr int SEM_SMEM_BYTES = 2 * SEM_STAGE + 1536;

__global__ void __launch_bounds__(256, 2)
sem_mma_kernel(const float* __restrict__ b1, const float* __restrict__ W2) {
    extern __shared__ char smem[];
    float* s_b1 = (float*)(smem + 2 * SEM_STAGE);
    float* s_w2 = s_b1 + 128;
    float* s_wr = s_w2 + 128;   // 64
    uint32_t smem_u32;
    SMEM_U32(smem_u32, smem);

    const int t = threadIdx.x, lane = t & 31, wid = t >> 5;
    const int wm = wid & 1, wn = wid >> 1;
    const int rowBase = blockIdx.x * 64;
    const __half* Zh = &g_z_h[0][0][0];   // [40000][512]

    if (t < 128) { s_b1[t] = b1[t]; s_w2[t] = W2[t]; }
    if (t < 64) s_wr[t] = 0.f;

    const int l_in  = lane & 7;
    const int l_t01 = (lane >> 3) & 1;
    const int l_t23 = lane >> 4;
    const uint32_t a_off0 = (uint32_t)(wm * 32 + l_in + l_t01 * 8) * 80 + l_t23 * 16;
    const uint32_t b_off0 = 5120u + (uint32_t)(wn * 32 + l_in + (lane >> 4) * 8) * 80
                          + ((lane >> 3) & 1) * 16;

    auto cp_stage = [&](int kc, int buf) {
        uint32_t base = smem_u32 + buf * SEM_STAGE;
        {
            int row = t >> 2, q = t & 3;
            CP_ASYNC16(base + (uint32_t)row * 80 + q * 16,
                       Zh + (rowBase + row) * HD + kc * 32 + q * 8);
        }
#pragma unroll
        for (int j = 0; j < 2; j++) {
            int idx = t + j * 256;
            int row = idx >> 2, q = idx & 3;
            CP_ASYNC16(base + 5120 + (uint32_t)row * 80 + q * 16,
                       &g_W1t_h[row][kc * 32 + q * 8]);
        }
    };

    float d[2][4][4] = {};

    cp_stage(0, 0);
    CP_COMMIT();

    for (int kc = 0; kc < 16; kc++) {
        const int cur = kc & 1;
        if (kc < 15) {
            cp_stage(kc + 1, cur ^ 1);
            CP_COMMIT();
            CP_WAIT(1);
        } else {
            CP_WAIT(0);
        }
        __syncthreads();

        const uint32_t bufb = smem_u32 + cur * SEM_STAGE;
#pragma unroll
        for (int ks = 0; ks < 2; ks++) {
            const uint32_t kb = (uint32_t)ks * 32;
            uint32_t ah[2][4], bh[2][4];
#pragma unroll
            for (int mi = 0; mi < 2; mi++)
                LDSM_X4(ah[mi], bufb + a_off0 + (uint32_t)(mi * 16) * 80 + kb);
#pragma unroll
            for (int p = 0; p < 2; p++)
                LDSM_X4(bh[p], bufb + b_off0 + (uint32_t)(p * 16) * 80 + kb);
#pragma unroll
            for (int mi = 0; mi < 2; mi++)
#pragma unroll
                for (int p = 0; p < 2; p++)
#pragma unroll
                    for (int q = 0; q < 2; q++) {
                        int ni = p * 2 + q;
                        uint32_t bq[2] = { bh[p][q * 2], bh[p][q * 2 + 1] };
                        MMA_F16(d[mi][ni], ah[mi], bq);
                    }
        }
        __syncthreads();
    }

    // epilogue: w[row] = sum_c tanh(acc + b1[c]) * W2[c]; fused wsum
#pragma unroll
    for (int mi = 0; mi < 2; mi++) {
#pragma unroll
        for (int half = 0; half < 2; half++) {
            float p = 0.f;
#pragma unroll
            for (int ni = 0; ni < 4; ni++) {
                int c = wn * 32 + ni * 8 + (lane & 3) * 2;
                p += fast_tanh(d[mi][ni][half * 2 + 0] + s_b1[c]) * s_w2[c];
                p += fast_tanh(d[mi][ni][half * 2 + 1] + s_b1[c + 1]) * s_w2[c + 1];
            }
            p += __shfl_xor_sync(0xffffffffu, p, 1);
            p += __shfl_xor_sync(0xffffffffu, p, 2);
            if ((lane & 3) == 0)
                atomicAdd(&s_wr[wm * 32 + mi * 16 + half * 8 + (lane >> 2)], p);
        }
    }
    __syncthreads();
    if (t < 64) {
        float v = s_wr[t];
        int grow = rowBase + t;
        float v0 = (grow < NN) ? v : 0.f;
        float v1 = (grow >= NN) ? v : 0.f;
#pragma unroll
        for (int off = 16; off; off >>= 1) {
            v0 += __shfl_xor_sync(0xffffffffu, v0, off);
            v1 += __shfl_xor_sync(0xffffffffu, v1, off);
        }
        if (lane == 0) {
            atomicAdd(&g_wsum[0], v0);
            atomicAdd(&g_wsum[1], v1);
        }
    }
}

__global__ void beta_kernel() {
    float a = g_wsum[0] / (float)NN;
    float b = g_wsum[1] / (float)NN;
    float m = fmaxf(a, b);
    float ea = __expf(a - m), eb = __expf(b - m);
    float s = ea + eb;
    g_beta[0] = ea / s;
    g_beta[1] = eb / s;
}

// ---------------- prediction via fp16 MMA -----------------------------------
constexpr int PRED_SMEM_BYTES = 256 * 80;

__global__ void __launch_bounds__(256)
pred_mma_kernel(const float* __restrict__ pw, const float* __restrict__ pb,
                float* __restrict__ out) {
    extern __shared__ char smem[];
    uint32_t smem_u32;
    SMEM_U32(smem_u32, smem);

    const int t = threadIdx.x, lane = t & 31, wid = t >> 5;
    const int rowBase = blockIdx.x * 256;
    const float b0 = g_beta[0], b1 = g_beta[1];

    const int l_in  = lane & 7;
    const int l_t01 = (lane >> 3) & 1;
    const int l_t23 = lane >> 4;
    const uint32_t a_off0 = (uint32_t)(wid * 32 + l_in + l_t01 * 8) * 80 + l_t23 * 16;

    const int n_col = lane >> 2;          // 0..7 (valid < CC)
    const bool nval = n_col < CC;

    float d[2][4] = {};

    for (int kc = 0; kc < 16; kc++) {
        {
            int grow = rowBase + t;
            uint4 o[4];
            if (grow < NN) {
                const uint4* z0p = (const uint4*)&g_z_h[0][grow][kc * 32];
                const uint4* z1p = (const uint4*)&g_z_h[1][grow][kc * 32];
#pragma unroll
                for (int w = 0; w < 4; w++) {
                    uint4 za = z0p[w], zb = z1p[w];
                    o[w].x = comb2(za.x, zb.x, b0, b1);
                    o[w].y = comb2(za.y, zb.y, b0, b1);
                    o[w].z = comb2(za.z, zb.z, b0, b1);
                    o[w].w = comb2(za.w, zb.w, b0, b1);
                }
            } else {
#pragma unroll
                for (int w = 0; w < 4; w++) o[w] = make_uint4(0, 0, 0, 0);
            }
            char* dstp = smem + t * 80;
#pragma unroll
            for (int w = 0; w < 4; w++) *(uint4*)(dstp + w * 16) = o[w];
        }
        __syncthreads();

#pragma unroll
        for (int ks = 0; ks < 2; ks++) {
            uint32_t a0[4], a1[4];
            LDSM_X4(a0, smem_u32 + a_off0 + (uint32_t)ks * 32);
            LDSM_X4(a1, smem_u32 + a_off0 + 16u * 80 + (uint32_t)ks * 32);
            int kk = kc * 32 + ks * 16 + (lane & 3) * 2;
            uint32_t br[2] = {0, 0};
            if (nval) {
                __half2 q0 = __floats2half2_rn(pw[kk * CC + n_col], pw[(kk + 1) * CC + n_col]);
                __half2 q1 = __floats2half2_rn(pw[(kk + 8) * CC + n_col], pw[(kk + 9) * CC + n_col]);
                br[0] = *(uint32_t*)&q0;
                br[1] = *(uint32_t*)&q1;
            }
            MMA_F16(d[0], a0, br);
            MMA_F16(d[1], a1, br);
        }
        __syncthreads();
    }

#pragma unroll
    for (int mi = 0; mi < 2; mi++) {
#pragma unroll
        for (int half = 0; half < 2; half++) {
            int grow = rowBase + wid * 32 + mi * 16 + half * 8 + (lane >> 2);
            int c0 = (lane & 3) * 2;
            if (grow < NN) {
                if (c0 < CC)     out[grow * CC + c0]     = d[mi][half * 2 + 0] + pb[c0];
                if (c0 + 1 < CC) out[grow * CC + c0 + 1] = d[mi][half * 2 + 1] + pb[c0 + 1];
            }
        }
    }
}

// ---------------- launch ----------------
extern "C" void kernel_launch(void* const* d_in, const int* in_sizes, int n_in,
                              void* d_out, int out_size) {
    const float* h      = (const float*)d_in[0];
    const int*   src    = (const int*)d_in[1];
    const int*   dst    = (const int*)d_in[2];
    const float* W      = (const float*)d_in[3];
    const float* attn_l = (const float*)d_in[4];
    const float* attn_r = (const float*)d_in[5];
    const float* bias_g = (const float*)d_in[6];
    const float* sem_W1 = (const float*)d_in[7];
    const float* sem_b1 = (const float*)d_in[8];
    const float* sem_W2 = (const float*)d_in[9];
    const float* pred_W = (const float*)d_in[10];
    const float* pred_b = (const float*)d_in[11];
    float* out = (float*)d_out;

    static cudaStream_t s2 = nullptr;
    static cudaEvent_t ev_fork = nullptr, ev_join = nullptr;
    if (s2 == nullptr) {
        cudaStreamCreateWithFlags(&s2, cudaStreamNonBlocking);
        cudaEventCreateWithFlags(&ev_fork, cudaEventDisableTiming);
        cudaEventCreateWithFlags(&ev_join, cudaEventDisableTiming);
    }

    cudaFuncSetAttribute(feat_mma_kernel,
                         cudaFuncAttributeMaxDynamicSharedMemorySize, FEAT_SMEM_BYTES);
    cudaFuncSetAttribute(sem_mma_kernel,
                         cudaFuncAttributeMaxDynamicSharedMemorySize, SEM_SMEM_BYTES);
    cudaFuncSetAttribute(pred_mma_kernel,
                         cudaFuncAttributeMaxDynamicSharedMemorySize, PRED_SMEM_BYTES);

    void* p_deg = nullptr;
    void* p_ws  = nullptr;
    cudaGetSymbolAddress(&p_deg, g_deg);
    cudaGetSymbolAddress(&p_ws, g_wsum);
    cudaMemsetAsync(p_deg, 0, sizeof(int) * MM * NN, 0);        // launch 1
    cudaMemsetAsync(p_ws, 0, sizeof(float) * MM, 0);            // launch 2

    conv_h_kernel<<<(NPAD * FF / 8 + 255) / 256, 256>>>(h);     // launch 3
    {
        dim3 grid(HD / 32, FF / 32, MM);
        conv_w_kernel<<<grid, dim3(32, 8)>>>(W);                // launch 4
    }

    cudaEventRecord(ev_fork, 0);
    cudaStreamWaitEvent(s2, ev_fork, 0);
    {
        dim3 grid((EE + 255) / 256, MM);
        count_kernel<<<grid, 256, 0, s2>>>(dst);                // launch 5
    }
    {
        dim3 grid((NN + 127) / 128, HD / 128, MM);
        feat_mma_kernel<<<grid, 256, FEAT_SMEM_BYTES>>>(attn_l, attn_r);  // launch 6
    }
    conv_w1t_kernel<<<dim3(HIDN / 32, HD / 32), dim3(32, 8)>>>(sem_W1);
    scan_partial<<<dim3(NB, MM), 256, 0, s2>>>();
    scan_mid<<<MM, 128, 0, s2>>>();
    scan_final<<<dim3(NB, MM), 256, 0, s2>>>();
    {
        dim3 grid((EE + 255) / 256, MM);
        scatter_kernel<<<grid, 256, 0, s2>>>(src, dst);
    }
    cudaEventRecord(ev_join, s2);
    cudaStreamWaitEvent(0, ev_join, 0);

    {
        dim3 grid(NN, MM);
        agg_kernel<<<grid, 128>>>(bias_g);
    }
    sem_mma_kernel<<<(MM * NN) / 64, 256, SEM_SMEM_BYTES>>>(sem_b1, sem_W2);
    beta_kernel<<<1, 1>>>();
    pred_mma_kernel<<<(NN + 255) / 256, 256, PRED_SMEM_BYTES>>>(pred_W, pred_b, out);
}